// round 10
// baseline (speedup 1.0000x reference)
#include <cuda_runtime.h>
#include <cuda_bf16.h>
#include <cstdint>

// MvCnnDownLayer via mma.sync bf16 2-split (3 products, fp32 accum),
// W-split across 2-CTA clusters, OC-split across warps (no reduce stage):
//   out[b,h] = relu(conv1dW(in[b,h] + out[b,h-1]) + bias)
// B=16,H=256,W=256,C=32,K=5. Grid 32 = 16 clusters x 2 CTAs, 512 thr.
// CTA owns 128 x (8 m16-tiles); A = X row bf16 hi/lo planes, 132 rows
// (2 halo each side), 80B stride. Warp (tile, ochalf): all 10 k-tiles,
// 16 oc -> 60 MMA, private accumulators, private epilogue patch.
// One barrier.cluster per row is the ONLY sync (cluster-wide incl. CTA-local).

#define Bn 16
#define Hn 256
#define Wn 256
#define Cn 32
#define NT 512

#define ROWB 80u                    // bytes per A/W SMEM row (32 bf16 + pad)
#define APAR (132u * ROWB)          // per parity per plane
#define OFF_AH 0u
#define OFF_AL 21120u
#define OFF_WH 42240u               // 160 rows x 80B
#define OFF_WL 55040u
#define SMEM_BYTES 67840u

__device__ __forceinline__ void ldm4(uint32_t a, uint32_t r[4]) {
    asm volatile("ldmatrix.sync.aligned.m8n8.x4.shared.b16 {%0,%1,%2,%3}, [%4];"
                 : "=r"(r[0]), "=r"(r[1]), "=r"(r[2]), "=r"(r[3]) : "r"(a));
}
__device__ __forceinline__ void ldm4t(uint32_t a, uint32_t r[4]) {
    asm volatile("ldmatrix.sync.aligned.m8n8.x4.trans.shared.b16 {%0,%1,%2,%3}, [%4];"
                 : "=r"(r[0]), "=r"(r[1]), "=r"(r[2]), "=r"(r[3]) : "r"(a));
}
__device__ __forceinline__ void mma16816(float d[4], const uint32_t a[4],
                                         uint32_t b0, uint32_t b1) {
    asm volatile("mma.sync.aligned.m16n8k16.row.col.f32.bf16.bf16.f32 "
                 "{%0,%1,%2,%3}, {%4,%5,%6,%7}, {%8,%9}, {%0,%1,%2,%3};"
                 : "+f"(d[0]), "+f"(d[1]), "+f"(d[2]), "+f"(d[3])
                 : "r"(a[0]), "r"(a[1]), "r"(a[2]), "r"(a[3]), "r"(b0), "r"(b1));
}
__device__ __forceinline__ uint32_t pack2(float lo, float hi) {
    uint32_t r;
    asm("cvt.rn.satfinite.bf16x2.f32 %0, %1, %2;" : "=r"(r) : "f"(hi), "f"(lo));
    return r;
}
__device__ __forceinline__ float bf16rt(float x) {
    return __bfloat162float(__float2bfloat16(x));
}

__global__ void __cluster_dims__(2, 1, 1) __launch_bounds__(NT, 1)
mvcnn_mma3_kernel(const float* __restrict__ in, const float* __restrict__ wg,
                  const float* __restrict__ bias, float* __restrict__ out)
{
    extern __shared__ char smb[];
    const uint32_t smem = (uint32_t)__cvta_generic_to_shared(smb);

    const int tid    = threadIdx.x;
    const int lane   = tid & 31;
    const int wid    = tid >> 5;         // 0..15
    const int tile   = wid & 7;          // m16-tile within segment
    const int ochalf = wid >> 3;         // 0: oc 0-15, 1: oc 16-31
    const int b      = blockIdx.x >> 1;
    const int rank   = blockIdx.x & 1;
    const int seg    = rank * 128;

    const int q   = lane & 3;
    const int xr  = lane >> 2;
    const int ocq = ochalf * 16 + q * 2; // this thread's oc pairs: ocq, ocq+8
    const int xl0 = tile * 16 + xr;      // local x; this thread: xl0, xl0+8

    // --- stage weights: row = k*32+c, col = oc; bf16 hi/lo planes ---
    for (int idx = tid; idx < 5 * Cn * Cn; idx += NT) {
        int oc = idx & 31, ck = idx >> 5, k = ck % 5, c = ck / 5;
        float w  = wg[idx];
        float hf = bf16rt(w);
        uint32_t off = (uint32_t)(k * 32 + c) * ROWB + (uint32_t)oc * 2u;
        *(__nv_bfloat16*)(smb + OFF_WH + off) = __float2bfloat16(hf);
        *(__nv_bfloat16*)(smb + OFF_WL + off) = __float2bfloat16(w - hf);
    }

    // --- zero edge-of-image halo rows (both parities, both planes) ---
    // rank0: ax 0,1 (x=-2,-1); rank1: ax 130,131 (x=256,257)
    if (tid < 160) {
        int word = tid % 20;
        int r    = tid / 20;             // row(2) x parity(2) x plane(2)
        int rr   = r & 1;
        int par  = (r >> 1) & 1;
        int pl   = r >> 2;
        uint32_t ax   = (rank == 0) ? (uint32_t)rr : (uint32_t)(130 + rr);
        uint32_t base = (pl ? OFF_AL : OFF_AH) + (uint32_t)par * APAR;
        *(uint32_t*)(smb + base + ax * ROWB + (uint32_t)word * 4u) = 0u;
    }

    const size_t bHW = (size_t)b * Hn * Wn;

    // --- row-0 interior halo from global (parity 0) ---
    // rank0: ax 130,131 <- x 128,129 ; rank1: ax 0,1 <- x 126,127
    if (tid < 32) {
        int r  = tid >> 4;               // 0..1
        int cp = tid & 15;               // channel pair
        int gx = (rank == 0) ? (128 + r) : (126 + r);
        uint32_t ax = (rank == 0) ? (uint32_t)(130 + r) : (uint32_t)r;
        float2 v = *(const float2*)(in + (bHW + gx) * Cn + cp * 2);
        float h0 = bf16rt(v.x), h1 = bf16rt(v.y);
        uint32_t off = ax * ROWB + (uint32_t)cp * 4u;
        *(uint32_t*)(smb + OFF_AH + off) = pack2(h0, h1);
        *(uint32_t*)(smb + OFF_AL + off) = pack2(v.x - h0, v.y - h1);
    }

    // --- bias for this thread's 4 channels ---
    float bv0[2], bv1[2];
#pragma unroll
    for (int j = 0; j < 2; ++j) {
        float2 t = *(const float2*)(bias + ocq + 8 * j);
        bv0[j] = t.x; bv1[j] = t.y;
    }

    const uint32_t frag_base = (uint32_t)(lane & 15) * ROWB + (uint32_t)(lane >> 4) * 16u;

    // --- row-0 interior state = in[0]: every warp fills its own 16x x 16oc patch ---
#pragma unroll
    for (int s = 0; s < 2; ++s) {
        int lx = xl0 + s * 8;
        const float* ip = in + (bHW + (seg + lx)) * Cn;
#pragma unroll
        for (int j = 0; j < 2; ++j) {
            int oc = ocq + 8 * j;
            float2 v = *(const float2*)(ip + oc);
            float h0 = bf16rt(v.x), h1 = bf16rt(v.y);
            uint32_t off = (uint32_t)(lx + 2) * ROWB + (uint32_t)oc * 2u;
            *(uint32_t*)(smb + OFF_AH + off) = pack2(h0, h1);
            *(uint32_t*)(smb + OFF_AL + off) = pack2(v.x - h0, v.y - h1);
        }
    }
    __syncthreads();

    // --- remote SMEM base of partner CTA ---
    uint32_t rbase;
    asm("mapa.shared::cluster.u32 %0, %1, %2;" : "=r"(rbase) : "r"(smem), "r"(rank ^ 1));

    const uint32_t bhalf = (uint32_t)ochalf * 32u;

    for (int i = 0; i < Hn; ++i) {
        const int  p    = i & 1;
        const bool more = (i + 1 < Hn);

        // prefetch next input row (this warp's own patch; hidden behind MMAs)
        float2 pf[2][2];
        if (more) {
#pragma unroll
            for (int s = 0; s < 2; ++s) {
                const float* ip = in + (bHW + (size_t)(i + 1) * Wn + (seg + xl0 + s * 8)) * Cn;
#pragma unroll
                for (int j = 0; j < 2; ++j) pf[s][j] = *(const float2*)(ip + ocq + 8 * j);
            }
        }

        float d[2][4];
#pragma unroll
        for (int j = 0; j < 2; ++j)
#pragma unroll
            for (int e = 0; e < 4; ++e) d[j][e] = 0.f;

        const uint32_t aH = smem + OFF_AH + (uint32_t)p * APAR + frag_base;
        const uint32_t aL = smem + OFF_AL + (uint32_t)p * APAR + frag_base;
        const uint32_t wH = smem + OFF_WH + frag_base + bhalf;
        const uint32_t wL = smem + OFF_WL + frag_base + bhalf;

#pragma unroll
        for (int kt = 0; kt < 10; ++kt) {
            const int k = kt >> 1, ch = kt & 1;
            const uint32_t aoff = (uint32_t)(tile * 16 + k) * ROWB + (uint32_t)ch * 32u;
            const uint32_t boff = (uint32_t)kt * (16u * ROWB);
            uint32_t ah[4], al[4], bh[4], bl[4];
            ldm4(aH + aoff, ah);
            ldm4(aL + aoff, al);
            ldm4t(wH + boff, bh);          // this warp's 16 oc
            ldm4t(wL + boff, bl);
            mma16816(d[0], ah, bh[0], bh[1]);
            mma16816(d[1], ah, bh[2], bh[3]);
            mma16816(d[0], ah, bl[0], bl[1]);
            mma16816(d[1], ah, bl[2], bl[3]);
            mma16816(d[0], al, bh[0], bh[1]);
            mma16816(d[1], al, bh[2], bh[3]);
        }

        // --- epilogue: relu(d+bias), STG, next state (+remote edge halo) ---
        float* op = out + (bHW + (size_t)i * Wn) * Cn;
        const uint32_t wAH = OFF_AH + (uint32_t)(p ^ 1) * APAR;
        const uint32_t wAL = OFF_AL + (uint32_t)(p ^ 1) * APAR;
#pragma unroll
        for (int s = 0; s < 2; ++s) {
            const int lx = xl0 + s * 8;
            const bool edge = (rank == 0) ? (lx >= 126) : (lx < 2);
            const uint32_t rax = (rank == 0) ? (uint32_t)(lx - 126) : (uint32_t)(130 + lx);
#pragma unroll
            for (int j = 0; j < 2; ++j) {
                const int oc = ocq + 8 * j;
                float v0 = fmaxf(d[j][2 * s + 0] + bv0[j], 0.f);
                float v1 = fmaxf(d[j][2 * s + 1] + bv1[j], 0.f);
                *(float2*)(op + (size_t)(seg + lx) * Cn + oc) = make_float2(v0, v1);
                if (more) {
                    float xn0 = v0 + pf[s][j].x;
                    float xn1 = v1 + pf[s][j].y;
                    float h0 = bf16rt(xn0), h1 = bf16rt(xn1);
                    uint32_t ph = pack2(h0, h1);
                    uint32_t pl = pack2(xn0 - h0, xn1 - h1);
                    uint32_t off = (uint32_t)(lx + 2) * ROWB + (uint32_t)oc * 2u;
                    *(uint32_t*)(smb + wAH + off) = ph;
                    *(uint32_t*)(smb + wAL + off) = pl;
                    if (edge) {
                        uint32_t roff = rax * ROWB + (uint32_t)oc * 2u;
                        asm volatile("st.shared::cluster.b32 [%0], %1;"
                                     :: "r"(rbase + wAH + roff), "r"(ph) : "memory");
                        asm volatile("st.shared::cluster.b32 [%0], %1;"
                                     :: "r"(rbase + wAL + roff), "r"(pl) : "memory");
                    }
                }
            }
        }

        // single per-row sync: cluster-wide barrier (covers CTA-local ordering too,
        // releases local SMEM + remote halo stores)
        if (more)
            asm volatile("barrier.cluster.arrive.aligned;\n\tbarrier.cluster.wait.aligned;"
                         ::: "memory");
    }
}

extern "C" void kernel_launch(void* const* d_in, const int* in_sizes, int n_in,
                              void* d_out, int out_size)
{
    const float* in   = (const float*)d_in[0];
    const float* w    = (const float*)d_in[1];
    const float* bias = (const float*)d_in[2];
    float* out        = (float*)d_out;
    (void)in_sizes; (void)n_in; (void)out_size;

    cudaFuncSetAttribute(mvcnn_mma3_kernel,
                         cudaFuncAttributeMaxDynamicSharedMemorySize, SMEM_BYTES);
    mvcnn_mma3_kernel<<<dim3(Bn * 2), dim3(NT), SMEM_BYTES>>>(in, w, bias, out);
}

// round 11
// speedup vs baseline: 1.1421x; 1.1421x over previous
#include <cuda_runtime.h>
#include <cuda_bf16.h>
#include <cstdint>

// MvCnnDownLayer via mma.sync bf16 2-split (3 products, fp32 accum),
// W-split across 2-CTA clusters, OC-split across warps, reduce-free,
// product-split accumulators (chain depth 10) + hoisted Wh fragments:
//   out[b,h] = relu(conv1dW(in[b,h] + out[b,h-1]) + bias)
// B=16,H=256,W=256,C=32,K=5. Grid 32 = 16 clusters x 2 CTAs, 512 thr.
// Warp (tile 0-7, ochalf 0-1): all 10 k-tiles, 16 oc.
// Per kt: 6 MMAs into 6 distinct accumulator sets (dHH/dHL/dLH x 2 n8).
// Wh fragments loaded once per kernel (40 regs); Wl + A loaded per row.
// One barrier.cluster per row is the only sync.

#define Bn 16
#define Hn 256
#define Wn 256
#define Cn 32
#define NT 512

#define ROWB 80u                    // bytes per A/W SMEM row (32 bf16 + pad)
#define APAR (132u * ROWB)          // per parity per plane
#define OFF_AH 0u
#define OFF_AL 21120u
#define OFF_WH 42240u               // 160 rows x 80B
#define OFF_WL 55040u
#define SMEM_BYTES 67840u

__device__ __forceinline__ void ldm4(uint32_t a, uint32_t r[4]) {
    asm volatile("ldmatrix.sync.aligned.m8n8.x4.shared.b16 {%0,%1,%2,%3}, [%4];"
                 : "=r"(r[0]), "=r"(r[1]), "=r"(r[2]), "=r"(r[3]) : "r"(a));
}
__device__ __forceinline__ void ldm4t(uint32_t a, uint32_t r[4]) {
    asm volatile("ldmatrix.sync.aligned.m8n8.x4.trans.shared.b16 {%0,%1,%2,%3}, [%4];"
                 : "=r"(r[0]), "=r"(r[1]), "=r"(r[2]), "=r"(r[3]) : "r"(a));
}
__device__ __forceinline__ void mma16816(float d[4], const uint32_t a[4],
                                         uint32_t b0, uint32_t b1) {
    asm volatile("mma.sync.aligned.m16n8k16.row.col.f32.bf16.bf16.f32 "
                 "{%0,%1,%2,%3}, {%4,%5,%6,%7}, {%8,%9}, {%0,%1,%2,%3};"
                 : "+f"(d[0]), "+f"(d[1]), "+f"(d[2]), "+f"(d[3])
                 : "r"(a[0]), "r"(a[1]), "r"(a[2]), "r"(a[3]), "r"(b0), "r"(b1));
}
__device__ __forceinline__ uint32_t pack2(float lo, float hi) {
    uint32_t r;
    asm("cvt.rn.satfinite.bf16x2.f32 %0, %1, %2;" : "=r"(r) : "f"(hi), "f"(lo));
    return r;
}
__device__ __forceinline__ float bf16rt(float x) {
    return __bfloat162float(__float2bfloat16(x));
}

__global__ void __cluster_dims__(2, 1, 1) __launch_bounds__(NT, 1)
mvcnn_mma4_kernel(const float* __restrict__ in, const float* __restrict__ wg,
                  const float* __restrict__ bias, float* __restrict__ out)
{
    extern __shared__ char smb[];
    const uint32_t smem = (uint32_t)__cvta_generic_to_shared(smb);

    const int tid    = threadIdx.x;
    const int lane   = tid & 31;
    const int wid    = tid >> 5;         // 0..15
    const int tile   = wid & 7;          // m16-tile within segment
    const int ochalf = wid >> 3;         // 0: oc 0-15, 1: oc 16-31
    const int b      = blockIdx.x >> 1;
    const int rank   = blockIdx.x & 1;
    const int seg    = rank * 128;

    const int q   = lane & 3;
    const int xr  = lane >> 2;
    const int ocq = ochalf * 16 + q * 2; // this thread's oc pairs: ocq, ocq+8
    const int xl0 = tile * 16 + xr;      // local x; this thread: xl0, xl0+8

    // --- stage weights: row = k*32+c, col = oc; bf16 hi/lo planes ---
    for (int idx = tid; idx < 5 * Cn * Cn; idx += NT) {
        int oc = idx & 31, ck = idx >> 5, k = ck % 5, c = ck / 5;
        float w  = wg[idx];
        float hf = bf16rt(w);
        uint32_t off = (uint32_t)(k * 32 + c) * ROWB + (uint32_t)oc * 2u;
        *(__nv_bfloat16*)(smb + OFF_WH + off) = __float2bfloat16(hf);
        *(__nv_bfloat16*)(smb + OFF_WL + off) = __float2bfloat16(w - hf);
    }

    // --- zero edge-of-image halo rows (both parities, both planes) ---
    if (tid < 160) {
        int word = tid % 20;
        int r    = tid / 20;
        int rr   = r & 1;
        int par  = (r >> 1) & 1;
        int pl   = r >> 2;
        uint32_t ax   = (rank == 0) ? (uint32_t)rr : (uint32_t)(130 + rr);
        uint32_t base = (pl ? OFF_AL : OFF_AH) + (uint32_t)par * APAR;
        *(uint32_t*)(smb + base + ax * ROWB + (uint32_t)word * 4u) = 0u;
    }

    const size_t bHW = (size_t)b * Hn * Wn;

    // --- row-0 interior halo from global (parity 0) ---
    if (tid < 32) {
        int r  = tid >> 4;
        int cp = tid & 15;
        int gx = (rank == 0) ? (128 + r) : (126 + r);
        uint32_t ax = (rank == 0) ? (uint32_t)(130 + r) : (uint32_t)r;
        float2 v = *(const float2*)(in + (bHW + gx) * Cn + cp * 2);
        float h0 = bf16rt(v.x), h1 = bf16rt(v.y);
        uint32_t off = ax * ROWB + (uint32_t)cp * 4u;
        *(uint32_t*)(smb + OFF_AH + off) = pack2(h0, h1);
        *(uint32_t*)(smb + OFF_AL + off) = pack2(v.x - h0, v.y - h1);
    }

    // --- bias for this thread's 4 channels ---
    float bv0[2], bv1[2];
#pragma unroll
    for (int j = 0; j < 2; ++j) {
        float2 t = *(const float2*)(bias + ocq + 8 * j);
        bv0[j] = t.x; bv1[j] = t.y;
    }

    const uint32_t frag_base = (uint32_t)(lane & 15) * ROWB + (uint32_t)(lane >> 4) * 16u;

    // --- row-0 interior state = in[0]: every warp fills its own 16x x 16oc patch ---
#pragma unroll
    for (int s = 0; s < 2; ++s) {
        int lx = xl0 + s * 8;
        const float* ip = in + (bHW + (seg + lx)) * Cn;
#pragma unroll
        for (int j = 0; j < 2; ++j) {
            int oc = ocq + 8 * j;
            float2 v = *(const float2*)(ip + oc);
            float h0 = bf16rt(v.x), h1 = bf16rt(v.y);
            uint32_t off = (uint32_t)(lx + 2) * ROWB + (uint32_t)oc * 2u;
            *(uint32_t*)(smb + OFF_AH + off) = pack2(h0, h1);
            *(uint32_t*)(smb + OFF_AL + off) = pack2(v.x - h0, v.y - h1);
        }
    }
    __syncthreads();

    // --- remote SMEM base of partner CTA ---
    uint32_t rbase;
    asm("mapa.shared::cluster.u32 %0, %1, %2;" : "=r"(rbase) : "r"(smem), "r"(rank ^ 1));

    const uint32_t bhalf = (uint32_t)ochalf * 32u;
    const uint32_t wH = smem + OFF_WH + frag_base + bhalf;
    const uint32_t wL = smem + OFF_WL + frag_base + bhalf;

    // --- hoist Wh fragments (row-invariant): 10 kt x 4 regs ---
    uint32_t whf[10][4];
#pragma unroll
    for (int kt = 0; kt < 10; ++kt)
        ldm4t(wH + (uint32_t)kt * (16u * ROWB), whf[kt]);

    for (int i = 0; i < Hn; ++i) {
        const int  p    = i & 1;
        const bool more = (i + 1 < Hn);

        // prefetch next input row (own patch; hidden behind MMAs)
        float2 pf[2][2];
        if (more) {
#pragma unroll
            for (int s = 0; s < 2; ++s) {
                const float* ip = in + (bHW + (size_t)(i + 1) * Wn + (seg + xl0 + s * 8)) * Cn;
#pragma unroll
                for (int j = 0; j < 2; ++j) pf[s][j] = *(const float2*)(ip + ocq + 8 * j);
            }
        }

        // product-split accumulators: chain depth 10 each
        float dHH[2][4], dHL[2][4], dLH[2][4];
#pragma unroll
        for (int j = 0; j < 2; ++j)
#pragma unroll
            for (int e = 0; e < 4; ++e) { dHH[j][e] = 0.f; dHL[j][e] = 0.f; dLH[j][e] = 0.f; }

        const uint32_t aH = smem + OFF_AH + (uint32_t)p * APAR + frag_base;
        const uint32_t aL = smem + OFF_AL + (uint32_t)p * APAR + frag_base;

#pragma unroll
        for (int kt = 0; kt < 10; ++kt) {
            const int k = kt >> 1, ch = kt & 1;
            const uint32_t aoff = (uint32_t)(tile * 16 + k) * ROWB + (uint32_t)ch * 32u;
            uint32_t ah[4], al[4], bl[4];
            ldm4(aH + aoff, ah);
            ldm4(aL + aoff, al);
            ldm4t(wL + (uint32_t)kt * (16u * ROWB), bl);
            mma16816(dHH[0], ah, whf[kt][0], whf[kt][1]);
            mma16816(dHH[1], ah, whf[kt][2], whf[kt][3]);
            mma16816(dHL[0], ah, bl[0], bl[1]);
            mma16816(dHL[1], ah, bl[2], bl[3]);
            mma16816(dLH[0], al, whf[kt][0], whf[kt][1]);
            mma16816(dLH[1], al, whf[kt][2], whf[kt][3]);
        }

        // merge product terms
        float d[2][4];
#pragma unroll
        for (int j = 0; j < 2; ++j)
#pragma unroll
            for (int e = 0; e < 4; ++e)
                d[j][e] = dHH[j][e] + dHL[j][e] + dLH[j][e];

        // --- epilogue: relu(d+bias), STG, next state (+remote edge halo) ---
        float* op = out + (bHW + (size_t)i * Wn) * Cn;
        const uint32_t wAH = OFF_AH + (uint32_t)(p ^ 1) * APAR;
        const uint32_t wAL = OFF_AL + (uint32_t)(p ^ 1) * APAR;
#pragma unroll
        for (int s = 0; s < 2; ++s) {
            const int lx = xl0 + s * 8;
            const bool edge = (rank == 0) ? (lx >= 126) : (lx < 2);
            const uint32_t rax = (rank == 0) ? (uint32_t)(lx - 126) : (uint32_t)(130 + lx);
#pragma unroll
            for (int j = 0; j < 2; ++j) {
                const int oc = ocq + 8 * j;
                float v0 = fmaxf(d[j][2 * s + 0] + bv0[j], 0.f);
                float v1 = fmaxf(d[j][2 * s + 1] + bv1[j], 0.f);
                *(float2*)(op + (size_t)(seg + lx) * Cn + oc) = make_float2(v0, v1);
                if (more) {
                    float xn0 = v0 + pf[s][j].x;
                    float xn1 = v1 + pf[s][j].y;
                    float h0 = bf16rt(xn0), h1 = bf16rt(xn1);
                    uint32_t ph = pack2(h0, h1);
                    uint32_t pl = pack2(xn0 - h0, xn1 - h1);
                    uint32_t off = (uint32_t)(lx + 2) * ROWB + (uint32_t)oc * 2u;
                    *(uint32_t*)(smb + wAH + off) = ph;
                    *(uint32_t*)(smb + wAL + off) = pl;
                    if (edge) {
                        uint32_t roff = rax * ROWB + (uint32_t)oc * 2u;
                        asm volatile("st.shared::cluster.b32 [%0], %1;"
                                     :: "r"(rbase + wAH + roff), "r"(ph) : "memory");
                        asm volatile("st.shared::cluster.b32 [%0], %1;"
                                     :: "r"(rbase + wAL + roff), "r"(pl) : "memory");
                    }
                }
            }
        }

        // single per-row sync: cluster-wide barrier
        if (more)
            asm volatile("barrier.cluster.arrive.aligned;\n\tbarrier.cluster.wait.aligned;"
                         ::: "memory");
    }
}

extern "C" void kernel_launch(void* const* d_in, const int* in_sizes, int n_in,
                              void* d_out, int out_size)
{
    const float* in   = (const float*)d_in[0];
    const float* w    = (const float*)d_in[1];
    const float* bias = (const float*)d_in[2];
    float* out        = (float*)d_out;
    (void)in_sizes; (void)n_in; (void)out_size;

    cudaFuncSetAttribute(mvcnn_mma4_kernel,
                         cudaFuncAttributeMaxDynamicSharedMemorySize, SMEM_BYTES);
    mvcnn_mma4_kernel<<<dim3(Bn * 2), dim3(NT), SMEM_BYTES>>>(in, w, bias, out);
}

// round 12
// speedup vs baseline: 1.6317x; 1.4287x over previous
#include <cuda_runtime.h>
#include <cuda_bf16.h>
#include <cstdint>

// MvCnnDownLayer via mma.sync bf16 2-split (3 products, fp32 accum).
// W-split across 4-CTA clusters, oc-quarter warps, all W fragments hoisted:
//   out[b,h] = relu(conv1dW(in[b,h] + out[b,h-1]) + bias)
// B=16,H=256,W=256,C=32,K=5. Grid 64 = 16 clusters x 4 CTAs, 512 thr.
// CTA owns 64 x (4 m16-tiles); A = X row bf16 hi/lo planes, 68 rows
// (2 halo each side), 80B stride. Warp (tile 0-3, ocq 0-3): 10 k-tiles,
// 8 oc -> 30 MMA into 3 product-split accumulators (chain depth 10).
// Wh+Wl fragments hoisted (row-invariant, 40 regs) -> per-row LDSM = A only.
// One barrier.cluster per row is the only sync.

#define Bn 16
#define Hn 256
#define Wn 256
#define Cn 32
#define NT 512

#define ROWB 80u                    // bytes per A/W SMEM row (32 bf16 + pad)
#define APAR (68u * ROWB)           // 5440 per parity per plane
#define OFF_AH 0u
#define OFF_AL 10880u
#define OFF_WH 21760u               // 160 rows x 80B
#define OFF_WL 34560u
#define SMEM_BYTES 47360u

__device__ __forceinline__ void ldm4(uint32_t a, uint32_t r[4]) {
    asm volatile("ldmatrix.sync.aligned.m8n8.x4.shared.b16 {%0,%1,%2,%3}, [%4];"
                 : "=r"(r[0]), "=r"(r[1]), "=r"(r[2]), "=r"(r[3]) : "r"(a));
}
__device__ __forceinline__ void ldm2t(uint32_t a, uint32_t r[2]) {
    asm volatile("ldmatrix.sync.aligned.m8n8.x2.trans.shared.b16 {%0,%1}, [%2];"
                 : "=r"(r[0]), "=r"(r[1]) : "r"(a));
}
__device__ __forceinline__ void mma16816(float d[4], const uint32_t a[4],
                                         uint32_t b0, uint32_t b1) {
    asm volatile("mma.sync.aligned.m16n8k16.row.col.f32.bf16.bf16.f32 "
                 "{%0,%1,%2,%3}, {%4,%5,%6,%7}, {%8,%9}, {%0,%1,%2,%3};"
                 : "+f"(d[0]), "+f"(d[1]), "+f"(d[2]), "+f"(d[3])
                 : "r"(a[0]), "r"(a[1]), "r"(a[2]), "r"(a[3]), "r"(b0), "r"(b1));
}
__device__ __forceinline__ uint32_t pack2(float lo, float hi) {
    uint32_t r;
    asm("cvt.rn.satfinite.bf16x2.f32 %0, %1, %2;" : "=r"(r) : "f"(hi), "f"(lo));
    return r;
}
__device__ __forceinline__ float bf16rt(float x) {
    return __bfloat162float(__float2bfloat16(x));
}

__global__ void __cluster_dims__(4, 1, 1) __launch_bounds__(NT, 1)
mvcnn_mma5_kernel(const float* __restrict__ in, const float* __restrict__ wg,
                  const float* __restrict__ bias, float* __restrict__ out)
{
    extern __shared__ char smb[];
    const uint32_t smem = (uint32_t)__cvta_generic_to_shared(smb);

    const int tid  = threadIdx.x;
    const int lane = tid & 31;
    const int wid  = tid >> 5;          // 0..15
    const int tile = wid & 3;           // m16-tile within 64-x segment
    const int ocq4 = wid >> 2;          // oc quarter 0..3
    const int b    = blockIdx.x >> 2;
    const int rank = blockIdx.x & 3;
    const int seg  = rank * 64;

    const int q   = lane & 3;
    const int xr  = lane >> 2;
    const int ocq = ocq4 * 8 + q * 2;   // this thread's oc pair
    const int xl0 = tile * 16 + xr;     // local x; this thread: xl0, xl0+8

    // --- stage weights: row = k*32+c, col = oc; bf16 hi/lo planes ---
    for (int idx = tid; idx < 5 * Cn * Cn; idx += NT) {
        int oc = idx & 31, ck = idx >> 5, k = ck % 5, c = ck / 5;
        float w  = wg[idx];
        float hf = bf16rt(w);
        uint32_t off = (uint32_t)(k * 32 + c) * ROWB + (uint32_t)oc * 2u;
        *(__nv_bfloat16*)(smb + OFF_WH + off) = __float2bfloat16(hf);
        *(__nv_bfloat16*)(smb + OFF_WL + off) = __float2bfloat16(w - hf);
    }

    const size_t bHW = (size_t)b * Hn * Wn;

    // --- halo rows ax in {0,1,66,67}: interior -> load row 0 (parity 0);
    //     edge-of-image -> zero BOTH parities (never rewritten) ---
    if (tid < 128) {
        int par  = tid >> 6;            // 0,1
        int side = (tid >> 5) & 1;      // 0=left, 1=right
        int rr   = (tid >> 4) & 1;      // row within side
        int cp   = tid & 15;            // channel pair
        uint32_t ax = side ? (uint32_t)(66 + rr) : (uint32_t)rr;
        int gx = seg + (side ? 64 + rr : rr - 2);
        bool valid = (gx >= 0) && (gx < Wn);
        uint32_t off = (uint32_t)par * APAR + ax * ROWB + (uint32_t)cp * 4u;
        if (!valid) {
            *(uint32_t*)(smb + OFF_AH + off) = 0u;
            *(uint32_t*)(smb + OFF_AL + off) = 0u;
        } else if (par == 0) {
            float2 v = *(const float2*)(in + (bHW + gx) * Cn + cp * 2);
            float h0 = bf16rt(v.x), h1 = bf16rt(v.y);
            *(uint32_t*)(smb + OFF_AH + off) = pack2(h0, h1);
            *(uint32_t*)(smb + OFF_AL + off) = pack2(v.x - h0, v.y - h1);
        }
    }

    // --- bias for this thread's 2 channels ---
    float2 bvt = *(const float2*)(bias + ocq);
    const float bv0 = bvt.x, bv1 = bvt.y;

    const uint32_t frag_base = (uint32_t)(lane & 15) * ROWB + (uint32_t)(lane >> 4) * 16u;

    // --- row-0 interior state = in[0]: every warp fills its own 16x x 8oc patch ---
#pragma unroll
    for (int s = 0; s < 2; ++s) {
        int lx = xl0 + s * 8;
        const float* ip = in + (bHW + (seg + lx)) * Cn + ocq;
        float2 v = *(const float2*)ip;
        float h0 = bf16rt(v.x), h1 = bf16rt(v.y);
        uint32_t off = (uint32_t)(lx + 2) * ROWB + (uint32_t)ocq * 2u;
        *(uint32_t*)(smb + OFF_AH + off) = pack2(h0, h1);
        *(uint32_t*)(smb + OFF_AL + off) = pack2(v.x - h0, v.y - h1);
    }
    __syncthreads();

    // --- remote SMEM bases of neighbor CTAs ---
    uint32_t rbaseL = 0, rbaseR = 0;
    if (rank > 0)
        asm("mapa.shared::cluster.u32 %0, %1, %2;" : "=r"(rbaseL) : "r"(smem), "r"(rank - 1));
    if (rank < 3)
        asm("mapa.shared::cluster.u32 %0, %1, %2;" : "=r"(rbaseR) : "r"(smem), "r"(rank + 1));

    // --- hoist Wh + Wl fragments (row-invariant): 10 kt x 2 regs each ---
    const uint32_t wHb = smem + OFF_WH + frag_base + (uint32_t)ocq4 * 16u;
    const uint32_t wLb = smem + OFF_WL + frag_base + (uint32_t)ocq4 * 16u;
    uint32_t whf[10][2], wlf[10][2];
#pragma unroll
    for (int kt = 0; kt < 10; ++kt) {
        ldm2t(wHb + (uint32_t)kt * (16u * ROWB), whf[kt]);
        ldm2t(wLb + (uint32_t)kt * (16u * ROWB), wlf[kt]);
    }

    for (int i = 0; i < Hn; ++i) {
        const int  p    = i & 1;
        const bool more = (i + 1 < Hn);

        // prefetch next input row (own patch; hidden behind MMAs)
        float2 pf[2];
        if (more) {
#pragma unroll
            for (int s = 0; s < 2; ++s)
                pf[s] = *(const float2*)(in + (bHW + (size_t)(i + 1) * Wn
                                               + (seg + xl0 + s * 8)) * Cn + ocq);
        }

        // product-split accumulators: chain depth 10 each
        float dHH[4], dHL[4], dLH[4];
#pragma unroll
        for (int e = 0; e < 4; ++e) { dHH[e] = 0.f; dHL[e] = 0.f; dLH[e] = 0.f; }

        const uint32_t aH = smem + OFF_AH + (uint32_t)p * APAR + frag_base;
        const uint32_t aL = smem + OFF_AL + (uint32_t)p * APAR + frag_base;

#pragma unroll
        for (int kt = 0; kt < 10; ++kt) {
            const int k = kt >> 1, ch = kt & 1;
            const uint32_t aoff = (uint32_t)(tile * 16 + k) * ROWB + (uint32_t)ch * 32u;
            uint32_t ah[4], al[4];
            ldm4(aH + aoff, ah);
            ldm4(aL + aoff, al);
            mma16816(dHH, ah, whf[kt][0], whf[kt][1]);
            mma16816(dHL, ah, wlf[kt][0], wlf[kt][1]);
            mma16816(dLH, al, whf[kt][0], whf[kt][1]);
        }

        // --- epilogue: relu(sum + bias), STG, next state (+remote edge halo) ---
        float* op = out + (bHW + (size_t)i * Wn) * Cn;
        const uint32_t wAH = OFF_AH + (uint32_t)(p ^ 1) * APAR;
        const uint32_t wAL = OFF_AL + (uint32_t)(p ^ 1) * APAR;
#pragma unroll
        for (int s = 0; s < 2; ++s) {
            const int lx = xl0 + s * 8;
            float v0 = fmaxf(dHH[2 * s + 0] + dHL[2 * s + 0] + dLH[2 * s + 0] + bv0, 0.f);
            float v1 = fmaxf(dHH[2 * s + 1] + dHL[2 * s + 1] + dLH[2 * s + 1] + bv1, 0.f);
            *(float2*)(op + (size_t)(seg + lx) * Cn + ocq) = make_float2(v0, v1);
            if (more) {
                float xn0 = v0 + pf[s].x;
                float xn1 = v1 + pf[s].y;
                float h0 = bf16rt(xn0), h1 = bf16rt(xn1);
                uint32_t ph = pack2(h0, h1);
                uint32_t pl = pack2(xn0 - h0, xn1 - h1);
                uint32_t off = (uint32_t)(lx + 2) * ROWB + (uint32_t)ocq * 2u;
                *(uint32_t*)(smb + wAH + off) = ph;
                *(uint32_t*)(smb + wAL + off) = pl;
                // push to left neighbor: lx 0,1 -> their ax 66,67
                if (lx < 2 && rank > 0) {
                    uint32_t roff = (uint32_t)(66 + lx) * ROWB + (uint32_t)ocq * 2u;
                    asm volatile("st.shared::cluster.b32 [%0], %1;"
                                 :: "r"(rbaseL + wAH + roff), "r"(ph) : "memory");
                    asm volatile("st.shared::cluster.b32 [%0], %1;"
                                 :: "r"(rbaseL + wAL + roff), "r"(pl) : "memory");
                }
                // push to right neighbor: lx 62,63 -> their ax 0,1
                if (lx >= 62 && rank < 3) {
                    uint32_t roff = (uint32_t)(lx - 62) * ROWB + (uint32_t)ocq * 2u;
                    asm volatile("st.shared::cluster.b32 [%0], %1;"
                                 :: "r"(rbaseR + wAH + roff), "r"(ph) : "memory");
                    asm volatile("st.shared::cluster.b32 [%0], %1;"
                                 :: "r"(rbaseR + wAL + roff), "r"(pl) : "memory");
                }
            }
        }

        // single per-row sync: cluster-wide barrier (covers CTA-local ordering,
        // releases local SMEM + remote halo stores)
        if (more)
            asm volatile("barrier.cluster.arrive.aligned;\n\tbarrier.cluster.wait.aligned;"
                         ::: "memory");
    }
}

extern "C" void kernel_launch(void* const* d_in, const int* in_sizes, int n_in,
                              void* d_out, int out_size)
{
    const float* in   = (const float*)d_in[0];
    const float* w    = (const float*)d_in[1];
    const float* bias = (const float*)d_in[2];
    float* out        = (float*)d_out;
    (void)in_sizes; (void)n_in; (void)out_size;

    cudaFuncSetAttribute(mvcnn_mma5_kernel,
                         cudaFuncAttributeMaxDynamicSharedMemorySize, SMEM_BYTES);
    mvcnn_mma5_kernel<<<dim3(Bn * 4), dim3(NT), SMEM_BYTES>>>(in, w, bias, out);
}

// round 13
// speedup vs baseline: 1.6666x; 1.0214x over previous
#include <cuda_runtime.h>
#include <cuda_bf16.h>
#include <cstdint>

// MvCnnDownLayer via mma.sync bf16 2-split (3 products, fp32 accum).
// W-split across 8-CTA clusters, oc-quarter warps, all W fragments hoisted:
//   out[b,h] = relu(conv1dW(in[b,h] + out[b,h-1]) + bias)
// B=16,H=256,W=256,C=32,K=5. Grid 128 = 16 clusters x 8 CTAs, 256 thr.
// CTA owns 32 x (2 m16-tiles); A = X row bf16 hi/lo planes, 36 rows
// (2 halo each side), 80B stride. Warp (tile 0-1, ocq 0-3): 10 k-tiles,
// 8 oc -> 30 MMA into 3 product-split accumulators (chain depth 10).
// Wh+Wl fragments hoisted -> per-row LDSM = A only (20 ldm4/warp).
// One barrier.cluster per row is the only sync.

#define Bn 16
#define Hn 256
#define Wn 256
#define Cn 32
#define NT 256

#define ROWB 80u                    // bytes per A/W SMEM row (32 bf16 + pad)
#define APAR (36u * ROWB)           // 2880 per parity per plane
#define OFF_AH 0u
#define OFF_AL 5760u
#define OFF_WH 11520u               // 160 rows x 80B
#define OFF_WL 24320u
#define SMEM_BYTES 37120u

__device__ __forceinline__ void ldm4(uint32_t a, uint32_t r[4]) {
    asm volatile("ldmatrix.sync.aligned.m8n8.x4.shared.b16 {%0,%1,%2,%3}, [%4];"
                 : "=r"(r[0]), "=r"(r[1]), "=r"(r[2]), "=r"(r[3]) : "r"(a));
}
__device__ __forceinline__ void ldm2t(uint32_t a, uint32_t r[2]) {
    asm volatile("ldmatrix.sync.aligned.m8n8.x2.trans.shared.b16 {%0,%1}, [%2];"
                 : "=r"(r[0]), "=r"(r[1]) : "r"(a));
}
__device__ __forceinline__ void mma16816(float d[4], const uint32_t a[4],
                                         uint32_t b0, uint32_t b1) {
    asm volatile("mma.sync.aligned.m16n8k16.row.col.f32.bf16.bf16.f32 "
                 "{%0,%1,%2,%3}, {%4,%5,%6,%7}, {%8,%9}, {%0,%1,%2,%3};"
                 : "+f"(d[0]), "+f"(d[1]), "+f"(d[2]), "+f"(d[3])
                 : "r"(a[0]), "r"(a[1]), "r"(a[2]), "r"(a[3]), "r"(b0), "r"(b1));
}
__device__ __forceinline__ uint32_t pack2(float lo, float hi) {
    uint32_t r;
    asm("cvt.rn.satfinite.bf16x2.f32 %0, %1, %2;" : "=r"(r) : "f"(hi), "f"(lo));
    return r;
}
__device__ __forceinline__ float bf16rt(float x) {
    return __bfloat162float(__float2bfloat16(x));
}

__global__ void __cluster_dims__(8, 1, 1) __launch_bounds__(NT, 1)
mvcnn_mma6_kernel(const float* __restrict__ in, const float* __restrict__ wg,
                  const float* __restrict__ bias, float* __restrict__ out)
{
    extern __shared__ char smb[];
    const uint32_t smem = (uint32_t)__cvta_generic_to_shared(smb);

    const int tid  = threadIdx.x;
    const int lane = tid & 31;
    const int wid  = tid >> 5;          // 0..7
    const int tile = wid & 1;           // m16-tile within 32-x segment
    const int ocq4 = wid >> 1;          // oc quarter 0..3
    const int b    = blockIdx.x >> 3;
    const int rank = blockIdx.x & 7;
    const int seg  = rank * 32;

    const int q   = lane & 3;
    const int xr  = lane >> 2;
    const int ocq = ocq4 * 8 + q * 2;   // this thread's oc pair
    const int xl0 = tile * 16 + xr;     // local x; this thread: xl0, xl0+8

    // --- stage weights: row = k*32+c, col = oc; bf16 hi/lo planes ---
    for (int idx = tid; idx < 5 * Cn * Cn; idx += NT) {
        int oc = idx & 31, ck = idx >> 5, k = ck % 5, c = ck / 5;
        float w  = wg[idx];
        float hf = bf16rt(w);
        uint32_t off = (uint32_t)(k * 32 + c) * ROWB + (uint32_t)oc * 2u;
        *(__nv_bfloat16*)(smb + OFF_WH + off) = __float2bfloat16(hf);
        *(__nv_bfloat16*)(smb + OFF_WL + off) = __float2bfloat16(w - hf);
    }

    const size_t bHW = (size_t)b * Hn * Wn;

    // --- halo rows ax in {0,1,34,35}: interior -> load row 0 (parity 0);
    //     edge-of-image -> zero BOTH parities (never rewritten) ---
    if (tid < 128) {
        int par  = tid >> 6;            // 0,1
        int side = (tid >> 5) & 1;      // 0=left, 1=right
        int rr   = (tid >> 4) & 1;      // row within side
        int cp   = tid & 15;            // channel pair
        uint32_t ax = side ? (uint32_t)(34 + rr) : (uint32_t)rr;
        int gx = seg + (side ? 32 + rr : rr - 2);
        bool valid = (gx >= 0) && (gx < Wn);
        uint32_t off = (uint32_t)par * APAR + ax * ROWB + (uint32_t)cp * 4u;
        if (!valid) {
            *(uint32_t*)(smb + OFF_AH + off) = 0u;
            *(uint32_t*)(smb + OFF_AL + off) = 0u;
        } else if (par == 0) {
            float2 v = *(const float2*)(in + (bHW + gx) * Cn + cp * 2);
            float h0 = bf16rt(v.x), h1 = bf16rt(v.y);
            *(uint32_t*)(smb + OFF_AH + off) = pack2(h0, h1);
            *(uint32_t*)(smb + OFF_AL + off) = pack2(v.x - h0, v.y - h1);
        }
    }

    // --- bias for this thread's 2 channels ---
    float2 bvt = *(const float2*)(bias + ocq);
    const float bv0 = bvt.x, bv1 = bvt.y;

    const uint32_t frag_base = (uint32_t)(lane & 15) * ROWB + (uint32_t)(lane >> 4) * 16u;

    // --- row-0 interior state = in[0]: every warp fills its own 16x x 8oc patch ---
#pragma unroll
    for (int s = 0; s < 2; ++s) {
        int lx = xl0 + s * 8;
        const float* ip = in + (bHW + (seg + lx)) * Cn + ocq;
        float2 v = *(const float2*)ip;
        float h0 = bf16rt(v.x), h1 = bf16rt(v.y);
        uint32_t off = (uint32_t)(lx + 2) * ROWB + (uint32_t)ocq * 2u;
        *(uint32_t*)(smb + OFF_AH + off) = pack2(h0, h1);
        *(uint32_t*)(smb + OFF_AL + off) = pack2(v.x - h0, v.y - h1);
    }
    __syncthreads();

    // --- remote SMEM bases of neighbor CTAs ---
    uint32_t rbaseL = 0, rbaseR = 0;
    if (rank > 0)
        asm("mapa.shared::cluster.u32 %0, %1, %2;" : "=r"(rbaseL) : "r"(smem), "r"(rank - 1));
    if (rank < 7)
        asm("mapa.shared::cluster.u32 %0, %1, %2;" : "=r"(rbaseR) : "r"(smem), "r"(rank + 1));

    // --- hoist Wh + Wl fragments (row-invariant): 10 kt x 2 regs each ---
    const uint32_t wHb = smem + OFF_WH + frag_base + (uint32_t)ocq4 * 16u;
    const uint32_t wLb = smem + OFF_WL + frag_base + (uint32_t)ocq4 * 16u;
    uint32_t whf[10][2], wlf[10][2];
#pragma unroll
    for (int kt = 0; kt < 10; ++kt) {
        ldm2t(wHb + (uint32_t)kt * (16u * ROWB), whf[kt]);
        ldm2t(wLb + (uint32_t)kt * (16u * ROWB), wlf[kt]);
    }

    for (int i = 0; i < Hn; ++i) {
        const int  p    = i & 1;
        const bool more = (i + 1 < Hn);

        // prefetch next input row (own patch; hidden behind MMAs)
        float2 pf[2];
        if (more) {
#pragma unroll
            for (int s = 0; s < 2; ++s)
                pf[s] = *(const float2*)(in + (bHW + (size_t)(i + 1) * Wn
                                               + (seg + xl0 + s * 8)) * Cn + ocq);
        }

        // product-split accumulators: chain depth 10 each
        float dHH[4], dHL[4], dLH[4];
#pragma unroll
        for (int e = 0; e < 4; ++e) { dHH[e] = 0.f; dHL[e] = 0.f; dLH[e] = 0.f; }

        const uint32_t aH = smem + OFF_AH + (uint32_t)p * APAR + frag_base;
        const uint32_t aL = smem + OFF_AL + (uint32_t)p * APAR + frag_base;

#pragma unroll
        for (int kt = 0; kt < 10; ++kt) {
            const int k = kt >> 1, ch = kt & 1;
            const uint32_t aoff = (uint32_t)(tile * 16 + k) * ROWB + (uint32_t)ch * 32u;
            uint32_t ah[4], al[4];
            ldm4(aH + aoff, ah);
            ldm4(aL + aoff, al);
            mma16816(dHH, ah, whf[kt][0], whf[kt][1]);
            mma16816(dHL, ah, wlf[kt][0], wlf[kt][1]);
            mma16816(dLH, al, whf[kt][0], whf[kt][1]);
        }

        // --- epilogue: relu(sum + bias), STG, next state (+remote edge halo) ---
        float* op = out + (bHW + (size_t)i * Wn) * Cn;
        const uint32_t wAH = OFF_AH + (uint32_t)(p ^ 1) * APAR;
        const uint32_t wAL = OFF_AL + (uint32_t)(p ^ 1) * APAR;
#pragma unroll
        for (int s = 0; s < 2; ++s) {
            const int lx = xl0 + s * 8;
            float v0 = fmaxf(dHH[2 * s + 0] + dHL[2 * s + 0] + dLH[2 * s + 0] + bv0, 0.f);
            float v1 = fmaxf(dHH[2 * s + 1] + dHL[2 * s + 1] + dLH[2 * s + 1] + bv1, 0.f);
            *(float2*)(op + (size_t)(seg + lx) * Cn + ocq) = make_float2(v0, v1);
            if (more) {
                float xn0 = v0 + pf[s].x;
                float xn1 = v1 + pf[s].y;
                float h0 = bf16rt(xn0), h1 = bf16rt(xn1);
                uint32_t ph = pack2(h0, h1);
                uint32_t pl = pack2(xn0 - h0, xn1 - h1);
                uint32_t off = (uint32_t)(lx + 2) * ROWB + (uint32_t)ocq * 2u;
                *(uint32_t*)(smb + wAH + off) = ph;
                *(uint32_t*)(smb + wAL + off) = pl;
                // push to left neighbor: lx 0,1 -> their ax 34,35
                if (lx < 2 && rank > 0) {
                    uint32_t roff = (uint32_t)(34 + lx) * ROWB + (uint32_t)ocq * 2u;
                    asm volatile("st.shared::cluster.b32 [%0], %1;"
                                 :: "r"(rbaseL + wAH + roff), "r"(ph) : "memory");
                    asm volatile("st.shared::cluster.b32 [%0], %1;"
                                 :: "r"(rbaseL + wAL + roff), "r"(pl) : "memory");
                }
                // push to right neighbor: lx 30,31 -> their ax 0,1
                if (lx >= 30 && rank < 7) {
                    uint32_t roff = (uint32_t)(lx - 30) * ROWB + (uint32_t)ocq * 2u;
                    asm volatile("st.shared::cluster.b32 [%0], %1;"
                                 :: "r"(rbaseR + wAH + roff), "r"(ph) : "memory");
                    asm volatile("st.shared::cluster.b32 [%0], %1;"
                                 :: "r"(rbaseR + wAL + roff), "r"(pl) : "memory");
                }
            }
        }

        // single per-row sync: cluster-wide barrier (covers CTA-local ordering,
        // releases local SMEM + remote halo stores)
        if (more)
            asm volatile("barrier.cluster.arrive.aligned;\n\tbarrier.cluster.wait.aligned;"
                         ::: "memory");
    }
}

extern "C" void kernel_launch(void* const* d_in, const int* in_sizes, int n_in,
                              void* d_out, int out_size)
{
    const float* in   = (const float*)d_in[0];
    const float* w    = (const float*)d_in[1];
    const float* bias = (const float*)d_in[2];
    float* out        = (float*)d_out;
    (void)in_sizes; (void)n_in; (void)out_size;

    cudaFuncSetAttribute(mvcnn_mma6_kernel,
                         cudaFuncAttributeMaxDynamicSharedMemorySize, SMEM_BYTES);
    mvcnn_mma6_kernel<<<dim3(Bn * 8), dim3(NT), SMEM_BYTES>>>(in, w, bias, out);
}

// round 14
// speedup vs baseline: 1.8219x; 1.0932x over previous
#include <cuda_runtime.h>
#include <cuda_bf16.h>
#include <cstdint>

// MvCnnDownLayer via mma.sync bf16 2-split (3 products, fp32 accum).
// W-split across 8-CTA clusters, oc-quarter warps, W fragments hoisted,
// DEPTH-2 input prefetch (in[i+2] issued in row i) + early barrier-arrive:
//   out[b,h] = relu(conv1dW(in[b,h] + out[b,h-1]) + bias)
// B=16,H=256,W=256,C=32,K=5. Grid 128 = 16 clusters x 8 CTAs, 256 thr.
// CTA owns 32 x (2 m16-tiles); A = X row bf16 hi/lo planes, 36 rows
// (2 halo each side), 80B stride. Warp (tile 0-1, ocq 0-3): 10 k-tiles,
// 8 oc -> 30 MMA into 3 product-split accumulators (chain depth 10).
// One barrier.cluster per row is the only sync.

#define Bn 16
#define Hn 256
#define Wn 256
#define Cn 32
#define NT 256

#define ROWB 80u                    // bytes per A/W SMEM row (32 bf16 + pad)
#define APAR (36u * ROWB)           // 2880 per parity per plane
#define OFF_AH 0u
#define OFF_AL 5760u
#define OFF_WH 11520u               // 160 rows x 80B
#define OFF_WL 24320u
#define SMEM_BYTES 37120u

__device__ __forceinline__ void ldm4(uint32_t a, uint32_t r[4]) {
    asm volatile("ldmatrix.sync.aligned.m8n8.x4.shared.b16 {%0,%1,%2,%3}, [%4];"
                 : "=r"(r[0]), "=r"(r[1]), "=r"(r[2]), "=r"(r[3]) : "r"(a));
}
__device__ __forceinline__ void ldm2t(uint32_t a, uint32_t r[2]) {
    asm volatile("ldmatrix.sync.aligned.m8n8.x2.trans.shared.b16 {%0,%1}, [%2];"
                 : "=r"(r[0]), "=r"(r[1]) : "r"(a));
}
__device__ __forceinline__ void mma16816(float d[4], const uint32_t a[4],
                                         uint32_t b0, uint32_t b1) {
    asm volatile("mma.sync.aligned.m16n8k16.row.col.f32.bf16.bf16.f32 "
                 "{%0,%1,%2,%3}, {%4,%5,%6,%7}, {%8,%9}, {%0,%1,%2,%3};"
                 : "+f"(d[0]), "+f"(d[1]), "+f"(d[2]), "+f"(d[3])
                 : "r"(a[0]), "r"(a[1]), "r"(a[2]), "r"(a[3]), "r"(b0), "r"(b1));
}
__device__ __forceinline__ uint32_t pack2(float lo, float hi) {
    uint32_t r;
    asm("cvt.rn.satfinite.bf16x2.f32 %0, %1, %2;" : "=r"(r) : "f"(hi), "f"(lo));
    return r;
}
__device__ __forceinline__ float bf16rt(float x) {
    return __bfloat162float(__float2bfloat16(x));
}

__global__ void __cluster_dims__(8, 1, 1) __launch_bounds__(NT, 1)
mvcnn_mma7_kernel(const float* __restrict__ in, const float* __restrict__ wg,
                  const float* __restrict__ bias, float* __restrict__ out)
{
    extern __shared__ char smb[];
    const uint32_t smem = (uint32_t)__cvta_generic_to_shared(smb);

    const int tid  = threadIdx.x;
    const int lane = tid & 31;
    const int wid  = tid >> 5;          // 0..7
    const int tile = wid & 1;           // m16-tile within 32-x segment
    const int ocq4 = wid >> 1;          // oc quarter 0..3
    const int b    = blockIdx.x >> 3;
    const int rank = blockIdx.x & 7;
    const int seg  = rank * 32;

    const int q   = lane & 3;
    const int xr  = lane >> 2;
    const int ocq = ocq4 * 8 + q * 2;   // this thread's oc pair
    const int xl0 = tile * 16 + xr;     // local x; this thread: xl0, xl0+8

    // --- stage weights: row = k*32+c, col = oc; bf16 hi/lo planes ---
    for (int idx = tid; idx < 5 * Cn * Cn; idx += NT) {
        int oc = idx & 31, ck = idx >> 5, k = ck % 5, c = ck / 5;
        float w  = wg[idx];
        float hf = bf16rt(w);
        uint32_t off = (uint32_t)(k * 32 + c) * ROWB + (uint32_t)oc * 2u;
        *(__nv_bfloat16*)(smb + OFF_WH + off) = __float2bfloat16(hf);
        *(__nv_bfloat16*)(smb + OFF_WL + off) = __float2bfloat16(w - hf);
    }

    const size_t bHW = (size_t)b * Hn * Wn;

    // --- halo rows ax in {0,1,34,35}: interior -> load row 0 (parity 0);
    //     edge-of-image -> zero BOTH parities (never rewritten) ---
    if (tid < 128) {
        int par  = tid >> 6;            // 0,1
        int side = (tid >> 5) & 1;      // 0=left, 1=right
        int rr   = (tid >> 4) & 1;      // row within side
        int cp   = tid & 15;            // channel pair
        uint32_t ax = side ? (uint32_t)(34 + rr) : (uint32_t)rr;
        int gx = seg + (side ? 32 + rr : rr - 2);
        bool valid = (gx >= 0) && (gx < Wn);
        uint32_t off = (uint32_t)par * APAR + ax * ROWB + (uint32_t)cp * 4u;
        if (!valid) {
            *(uint32_t*)(smb + OFF_AH + off) = 0u;
            *(uint32_t*)(smb + OFF_AL + off) = 0u;
        } else if (par == 0) {
            float2 v = *(const float2*)(in + (bHW + gx) * Cn + cp * 2);
            float h0 = bf16rt(v.x), h1 = bf16rt(v.y);
            *(uint32_t*)(smb + OFF_AH + off) = pack2(h0, h1);
            *(uint32_t*)(smb + OFF_AL + off) = pack2(v.x - h0, v.y - h1);
        }
    }

    // --- bias for this thread's 2 channels ---
    float2 bvt = *(const float2*)(bias + ocq);
    const float bv0 = bvt.x, bv1 = bvt.y;

    const uint32_t frag_base = (uint32_t)(lane & 15) * ROWB + (uint32_t)(lane >> 4) * 16u;

    // --- row-0 interior state = in[0]: every warp fills its own 16x x 8oc patch ---
#pragma unroll
    for (int s = 0; s < 2; ++s) {
        int lx = xl0 + s * 8;
        const float* ip = in + (bHW + (seg + lx)) * Cn + ocq;
        float2 v = *(const float2*)ip;
        float h0 = bf16rt(v.x), h1 = bf16rt(v.y);
        uint32_t off = (uint32_t)(lx + 2) * ROWB + (uint32_t)ocq * 2u;
        *(uint32_t*)(smb + OFF_AH + off) = pack2(h0, h1);
        *(uint32_t*)(smb + OFF_AL + off) = pack2(v.x - h0, v.y - h1);
    }
    __syncthreads();

    // --- remote SMEM bases of neighbor CTAs ---
    uint32_t rbaseL = 0, rbaseR = 0;
    if (rank > 0)
        asm("mapa.shared::cluster.u32 %0, %1, %2;" : "=r"(rbaseL) : "r"(smem), "r"(rank - 1));
    if (rank < 7)
        asm("mapa.shared::cluster.u32 %0, %1, %2;" : "=r"(rbaseR) : "r"(smem), "r"(rank + 1));

    // --- hoist Wh + Wl fragments (row-invariant): 10 kt x 2 regs each ---
    const uint32_t wHb = smem + OFF_WH + frag_base + (uint32_t)ocq4 * 16u;
    const uint32_t wLb = smem + OFF_WL + frag_base + (uint32_t)ocq4 * 16u;
    uint32_t whf[10][2], wlf[10][2];
#pragma unroll
    for (int kt = 0; kt < 10; ++kt) {
        ldm2t(wHb + (uint32_t)kt * (16u * ROWB), whf[kt]);
        ldm2t(wLb + (uint32_t)kt * (16u * ROWB), wlf[kt]);
    }

    // --- depth-2 prefetch pipeline: cur = in[i+1] (in regs), issue in[i+2] ---
    float2 cur[2];
    {
        // preload in[1]
#pragma unroll
        for (int s = 0; s < 2; ++s)
            cur[s] = *(const float2*)(in + (bHW + (size_t)1 * Wn + (seg + xl0 + s * 8)) * Cn + ocq);
    }

    for (int i = 0; i < Hn; ++i) {
        const int  p    = i & 1;
        const bool more = (i + 1 < Hn);

        // issue prefetch for in[i+2] (consumed NEXT row -> full-row latency cover)
        float2 nxt[2];
        if (i + 2 < Hn) {
#pragma unroll
            for (int s = 0; s < 2; ++s)
                nxt[s] = *(const float2*)(in + (bHW + (size_t)(i + 2) * Wn
                                                + (seg + xl0 + s * 8)) * Cn + ocq);
        }

        // product-split accumulators: chain depth 10 each
        float dHH[4], dHL[4], dLH[4];
#pragma unroll
        for (int e = 0; e < 4; ++e) { dHH[e] = 0.f; dHL[e] = 0.f; dLH[e] = 0.f; }

        const uint32_t aH = smem + OFF_AH + (uint32_t)p * APAR + frag_base;
        const uint32_t aL = smem + OFF_AL + (uint32_t)p * APAR + frag_base;

#pragma unroll
        for (int kt = 0; kt < 10; ++kt) {
            const int k = kt >> 1, ch = kt & 1;
            const uint32_t aoff = (uint32_t)(tile * 16 + k) * ROWB + (uint32_t)ch * 32u;
            uint32_t ah[4], al[4];
            ldm4(aH + aoff, ah);
            ldm4(aL + aoff, al);
            mma16816(dHH, ah, whf[kt][0], whf[kt][1]);
            mma16816(dHL, ah, wlf[kt][0], wlf[kt][1]);
            mma16816(dLH, al, whf[kt][0], whf[kt][1]);
        }

        // --- epilogue: state-build FIRST (so barrier-arrive is early), STG after ---
        float v0s[2], v1s[2];
        const uint32_t wAH = OFF_AH + (uint32_t)(p ^ 1) * APAR;
        const uint32_t wAL = OFF_AL + (uint32_t)(p ^ 1) * APAR;
#pragma unroll
        for (int s = 0; s < 2; ++s) {
            const int lx = xl0 + s * 8;
            float v0 = fmaxf(dHH[2 * s + 0] + dHL[2 * s + 0] + dLH[2 * s + 0] + bv0, 0.f);
            float v1 = fmaxf(dHH[2 * s + 1] + dHL[2 * s + 1] + dLH[2 * s + 1] + bv1, 0.f);
            v0s[s] = v0; v1s[s] = v1;
            if (more) {
                float xn0 = v0 + cur[s].x;
                float xn1 = v1 + cur[s].y;
                float h0 = bf16rt(xn0), h1 = bf16rt(xn1);
                uint32_t ph = pack2(h0, h1);
                uint32_t pl = pack2(xn0 - h0, xn1 - h1);
                uint32_t off = (uint32_t)(lx + 2) * ROWB + (uint32_t)ocq * 2u;
                *(uint32_t*)(smb + wAH + off) = ph;
                *(uint32_t*)(smb + wAL + off) = pl;
                // push to left neighbor: lx 0,1 -> their ax 34,35
                if (lx < 2 && rank > 0) {
                    uint32_t roff = (uint32_t)(34 + lx) * ROWB + (uint32_t)ocq * 2u;
                    asm volatile("st.shared::cluster.b32 [%0], %1;"
                                 :: "r"(rbaseL + wAH + roff), "r"(ph) : "memory");
                    asm volatile("st.shared::cluster.b32 [%0], %1;"
                                 :: "r"(rbaseL + wAL + roff), "r"(pl) : "memory");
                }
                // push to right neighbor: lx 30,31 -> their ax 0,1
                if (lx >= 30 && rank < 7) {
                    uint32_t roff = (uint32_t)(lx - 30) * ROWB + (uint32_t)ocq * 2u;
                    asm volatile("st.shared::cluster.b32 [%0], %1;"
                                 :: "r"(rbaseR + wAH + roff), "r"(ph) : "memory");
                    asm volatile("st.shared::cluster.b32 [%0], %1;"
                                 :: "r"(rbaseR + wAL + roff), "r"(pl) : "memory");
                }
            }
        }

        // output store (fire-and-forget, off the inter-CTA critical path)
        float* op = out + (bHW + (size_t)i * Wn) * Cn;
#pragma unroll
        for (int s = 0; s < 2; ++s)
            *(float2*)(op + (size_t)(seg + xl0 + s * 8) * Cn + ocq)
                = make_float2(v0s[s], v1s[s]);

        // rotate prefetch pipeline
        cur[0] = nxt[0]; cur[1] = nxt[1];

        // single per-row sync: cluster-wide barrier
        if (more)
            asm volatile("barrier.cluster.arrive.aligned;\n\tbarrier.cluster.wait.aligned;"
                         ::: "memory");
    }
}

extern "C" void kernel_launch(void* const* d_in, const int* in_sizes, int n_in,
                              void* d_out, int out_size)
{
    const float* in   = (const float*)d_in[0];
    const float* w    = (const float*)d_in[1];
    const float* bias = (const float*)d_in[2];
    float* out        = (float*)d_out;
    (void)in_sizes; (void)n_in; (void)out_size;

    cudaFuncSetAttribute(mvcnn_mma7_kernel,
                         cudaFuncAttributeMaxDynamicSharedMemorySize, SMEM_BYTES);
    mvcnn_mma7_kernel<<<dim3(Bn * 8), dim3(NT), SMEM_BYTES>>>(in, w, bias, out);
}